// round 4
// baseline (speedup 1.0000x reference)
#include <cuda_runtime.h>

#define NN     10000
#define EE     320000
#define FINN   5
#define FOUT   64
#define MLPH   32
#define CC     27
#define HIDD   450
#define FINAL  128
#define SDIM   168          // 160 (j*5+i) + 5 (x-sum for b2 term) + pad
#define VLEN   (NN*CC)      // 270000
#define DEGCAP 96           // per-warp smem edge cache in GAT

// ---------------- scratch (no allocations allowed) ----------------
static __device__ int    g_deg[NN];
static __device__ int    g_off[NN + 1];
static __device__ int    g_rank[EE];
static __device__ int    g_esrc[EE];
static __device__ float4 g_edata[2 * EE];   // per sorted edge: {x0,x1,x2,x3},{x4,ea0,ea1,_}
static __device__ float  g_S[NN * SDIM];
static __device__ float  g_xl[NN * CC];
static __device__ float  g_asrc[NN];
static __device__ float  g_adst[NN];
static __device__ int    g_nnz;
static __device__ int    g_cidx[VLEN];
static __device__ float  g_cval[VLEN];
static __device__ float  g_hid[HIDD];

// ---------------- init ----------------
__global__ void k_init() {
    int i = blockIdx.x * blockDim.x + threadIdx.x;
    if (i < NN) g_deg[i] = 0;
    if (i < HIDD) g_hid[i] = 0.f;
    if (i == 0) g_nnz = 0;
}

// ---------------- CSR: histogram with per-edge rank ----------------
__global__ void k_hist(const int* __restrict__ ei) {
    int e = blockIdx.x * blockDim.x + threadIdx.x;
    if (e < EE) g_rank[e] = atomicAdd(&g_deg[__ldg(&ei[EE + e])], 1);
}

__global__ void k_scan() {
    const int PER = 40;
    int tid = threadIdx.x;
    int start = tid * PER;
    int local = 0;
    for (int i = 0; i < PER; i++) {
        int idx = start + i;
        if (idx < NN) local += g_deg[idx];
    }
    int lane = tid & 31, w = tid >> 5;
    int incl = local;
    for (int s = 1; s < 32; s <<= 1) {
        int t = __shfl_up_sync(0xffffffffu, incl, s);
        if (lane >= s) incl += t;
    }
    __shared__ int wsum[8];
    __shared__ int woff[8];
    if (lane == 31) wsum[w] = incl;
    __syncthreads();
    if (tid == 0) {
        int c = 0;
        for (int i = 0; i < 8; i++) { woff[i] = c; c += wsum[i]; }
    }
    __syncthreads();
    int run = incl - local + woff[w];
    for (int i = 0; i < PER; i++) {
        int idx = start + i;
        if (idx < NN) { g_off[idx] = run; run += g_deg[idx]; }
    }
    if (tid == 0) g_off[NN] = EE;
}

// atomic-free scatter: build dst-sorted packed edge records
__global__ void k_scatter(const int* __restrict__ ei, const float* __restrict__ x,
                          const float* __restrict__ ea) {
    int e = blockIdx.x * blockDim.x + threadIdx.x;
    if (e >= EE) return;
    int dst = __ldg(&ei[EE + e]);
    int slot = g_off[dst] + g_rank[e];
    int src = __ldg(&ei[e]);
    float2 eav = __ldg((const float2*)ea + e);
    const float* xp = x + src * FINN;
    float4 v0 = make_float4(__ldg(xp), __ldg(xp + 1), __ldg(xp + 2), __ldg(xp + 3));
    float4 v1 = make_float4(__ldg(xp + 4), eav.x, eav.y, 0.f);
    g_edata[2 * slot] = v0;
    g_edata[2 * slot + 1] = v1;
    g_esrc[slot] = src;
}

// ---------------- S build: warp per node, lane = j; streaming packed edges ----------------
__global__ void k_S(const float* __restrict__ w1, const float* __restrict__ b1) {
    __shared__ float w1s[2 * MLPH];
    __shared__ float b1s[MLPH];
    int tid = threadIdx.x;
    if (tid < 2 * MLPH) w1s[tid] = w1[tid];
    if (tid < MLPH)     b1s[tid] = b1[tid];
    __syncthreads();

    int n = blockIdx.x * 8 + (tid >> 5);
    int j = tid & 31;
    float wa = w1s[j], wb = w1s[MLPH + j], bb = b1s[j];

    float s0 = 0.f, s1 = 0.f, s2 = 0.f, s3 = 0.f, s4 = 0.f, xs = 0.f;
    int k0 = g_off[n], k1 = g_off[n + 1];
#pragma unroll 2
    for (int k = k0; k < k1; k++) {
        float4 A = __ldg(&g_edata[2 * k]);
        float4 B = __ldg(&g_edata[2 * k + 1]);
        float h = fmaxf(fmaf(B.y, wa, fmaf(B.z, wb, bb)), 0.f);
        s0 = fmaf(h, A.x, s0); s1 = fmaf(h, A.y, s1); s2 = fmaf(h, A.z, s2);
        s3 = fmaf(h, A.w, s3); s4 = fmaf(h, B.x, s4);
        if (j < FINN) {
            float xv = (j == 0) ? A.x : (j == 1) ? A.y : (j == 2) ? A.z : (j == 3) ? A.w : B.x;
            xs += xv;
        }
    }
    float* Sp = g_S + n * SDIM + j * 5;
    Sp[0] = s0; Sp[1] = s1; Sp[2] = s2; Sp[3] = s3; Sp[4] = s4;
    if (j < FINN) g_S[n * SDIM + 160 + j] = xs;
}

// ---------------- fused NNConv epilogue + GAT linear; 2 nodes per warp ----------------
__global__ void k_x1xl(const float* __restrict__ x, const float* __restrict__ w2,
                       const float* __restrict__ b2, const float* __restrict__ root,
                       const float* __restrict__ nbias, const float* __restrict__ gw,
                       const float* __restrict__ asv, const float* __restrict__ adv) {
    __shared__ float sS[8][2][SDIM];      // per-warp S rows for its 2 nodes
    __shared__ float x1s[16][FOUT];
    __shared__ float gws[FOUT * CC];
    __shared__ float avs[CC], avd[CC];
    __shared__ float nbs[FOUT];
    int tid = threadIdx.x;
    int w = tid >> 5, lane = tid & 31;
    int n0 = blockIdx.x * 16 + w * 2;     // grid 625 * 16 == NN exactly

    for (int i = tid; i < FOUT * CC; i += 256) gws[i] = __ldg(&gw[i]);
    if (tid < CC) { avs[tid] = __ldg(&asv[tid]); avd[tid] = __ldg(&adv[tid]); }
    if (tid < FOUT) nbs[tid] = __ldg(&nbias[tid]);
#pragma unroll
    for (int p = 0; p < 2; p++) {
        const float* Sp = g_S + (n0 + p) * SDIM;
        for (int i = lane; i < 165; i += 32) sS[w][p][i] = __ldg(Sp + i);
    }
    __syncthreads();

    int o0 = lane, o1 = lane + 32;
    float a00 = nbs[o0], a01 = nbs[o1], a10 = nbs[o0], a11 = nbs[o1];
    const float* xp0 = x + n0 * FINN;
    const float* xp1 = xp0 + FINN;
#pragma unroll
    for (int i = 0; i < FINN; i++) {
        float r0 = __ldg(&root[i * FOUT + o0]);
        float r1 = __ldg(&root[i * FOUT + o1]);
        float xi0 = __ldg(xp0 + i), xi1 = __ldg(xp1 + i);
        a00 = fmaf(xi0, r0, a00); a01 = fmaf(xi0, r1, a01);
        a10 = fmaf(xi1, r0, a10); a11 = fmaf(xi1, r1, a11);
    }
#pragma unroll 4
    for (int j = 0; j < MLPH; j++) {
#pragma unroll
        for (int i = 0; i < FINN; i++) {
            float w20 = __ldg(&w2[j * 320 + i * 64 + o0]);
            float w21 = __ldg(&w2[j * 320 + i * 64 + o1]);
            float sv0 = sS[w][0][j * 5 + i];
            float sv1 = sS[w][1][j * 5 + i];
            a00 = fmaf(sv0, w20, a00); a01 = fmaf(sv0, w21, a01);
            a10 = fmaf(sv1, w20, a10); a11 = fmaf(sv1, w21, a11);
        }
    }
#pragma unroll
    for (int i = 0; i < FINN; i++) {
        float b20 = __ldg(&b2[i * 64 + o0]);
        float b21 = __ldg(&b2[i * 64 + o1]);
        float sv0 = sS[w][0][160 + i], sv1 = sS[w][1][160 + i];
        a00 = fmaf(sv0, b20, a00); a01 = fmaf(sv0, b21, a01);
        a10 = fmaf(sv1, b20, a10); a11 = fmaf(sv1, b21, a11);
    }
    x1s[w * 2][o0] = fmaxf(a00, 0.f); x1s[w * 2][o1] = fmaxf(a01, 0.f);
    x1s[w * 2 + 1][o0] = fmaxf(a10, 0.f); x1s[w * 2 + 1][o1] = fmaxf(a11, 0.f);
    __syncwarp();

    int c = lane;
#pragma unroll
    for (int p = 0; p < 2; p++) {
        int n = n0 + p;
        float acc = 0.f;
        if (c < CC) {
#pragma unroll 8
            for (int o = 0; o < FOUT; o++)
                acc = fmaf(x1s[w * 2 + p][o], gws[o * CC + c], acc);
            g_xl[n * CC + c] = acc;
        }
        float vs = (c < CC) ? acc * avs[c] : 0.f;
        float vd = (c < CC) ? acc * avd[c] : 0.f;
        for (int s = 16; s; s >>= 1) {
            vs += __shfl_xor_sync(0xffffffffu, vs, s);
            vd += __shfl_xor_sync(0xffffffffu, vd, s);
        }
        if (lane == 0) { g_asrc[n] = vs; g_adst[n] = vd; }
    }
}

__device__ __forceinline__ float lrelu(float a) { return a > 0.f ? a : 0.2f * a; }

// ---------------- GAT: online softmax, smem edge cache, fused compaction ----------------
__global__ void k_gat(const float* __restrict__ gbias) {
    __shared__ float abuf[8][DEGCAP];
    __shared__ int   sbuf[8][DEGCAP];
    int w = threadIdx.x >> 5, lane = threadIdx.x & 31;
    int n = blockIdx.x * 8 + w;
    int k0 = g_off[n], k1 = g_off[n + 1];
    int deg = k1 - k0;
    bool fits = (deg <= DEGCAP);
    float ad = g_adst[n];
    float aself = lrelu(g_asrc[n] + ad);

    // single sweep: online (max, denom); spill (a, src) to smem
    float m = -1e30f, d = 0.f;
    for (int k = k0 + lane; k < k1; k += 32) {
        int s = __ldg(&g_esrc[k]);
        float a = lrelu(__ldg(&g_asrc[s]) + ad);
        if (fits) { abuf[w][k - k0] = a; sbuf[w][k - k0] = s; }
        float mn = fmaxf(m, a);
        d = fmaf(d, __expf(m - mn), __expf(a - mn));
        m = mn;
    }
    for (int s = 16; s; s >>= 1) {
        float m2 = __shfl_xor_sync(0xffffffffu, m, s);
        float d2 = __shfl_xor_sync(0xffffffffu, d, s);
        float mn = fmaxf(m, m2);
        d = fmaf(d, __expf(m - mn), d2 * __expf(m2 - mn));
        m = mn;
    }
    {
        float mn = fmaxf(m, aself);
        d = fmaf(d, __expf(m - mn), __expf(aself - mn));
        m = mn;
    }
    float inv = 1.f / d;

    int c = lane;
    float out = (c < CC) ? __expf(aself - m) * inv * __ldg(&g_xl[n * CC + c]) : 0.f;
    __syncwarp();

    if (fits) {
#pragma unroll 4
        for (int i = 0; i < deg; i++) {
            float wv = __expf(abuf[w][i] - m) * inv;
            int si = sbuf[w][i];
            if (c < CC) out = fmaf(wv, __ldg(&g_xl[si * CC + c]), out);
        }
    } else {
        for (int k = k0; k < k1; k++) {
            int s = __ldg(&g_esrc[k]);
            float wv = __expf(lrelu(__ldg(&g_asrc[s]) + ad) - m) * inv;
            if (c < CC) out = fmaf(wv, __ldg(&g_xl[s * CC + c]), out);
        }
    }

    // epilogue relu + warp-aggregated compaction of nonzeros
    float r = 0.f;
    bool pred = false;
    if (c < CC) {
        r = out + __ldg(&gbias[c]);
        pred = (r > 0.f);
    }
    unsigned mask = __ballot_sync(0xffffffffu, pred);
    int cnt = __popc(mask);
    if (cnt) {
        int leader = __ffs(mask) - 1;
        int base = 0;
        if (lane == leader) base = atomicAdd(&g_nnz, cnt);
        base = __shfl_sync(0xffffffffu, base, leader);
        if (pred) {
            int off = __popc(mask & ((1u << lane) - 1));
            g_cidx[base + off] = n * CC + c;
            g_cval[base + off] = r;
        }
    }
}

// ---------------- fc1: compacted rows, float2 columns, 4-row unroll ----------------
__global__ void k_fc1(const float* __restrict__ w) {
    int t = threadIdx.x;
    if (t >= 225) return;                 // 225 float2 = 450 columns
    int nnz = g_nnz;
    int per = (nnz + gridDim.x - 1) / gridDim.x;
    int i0 = blockIdx.x * per;
    int i1 = i0 + per; if (i1 > nnz) i1 = nnz;
    float ax = 0.f, ay = 0.f;
    int i = i0;
    for (; i + 4 <= i1; i += 4) {
        int r0 = __ldg(&g_cidx[i]),     r1 = __ldg(&g_cidx[i + 1]);
        int r2 = __ldg(&g_cidx[i + 2]), r3 = __ldg(&g_cidx[i + 3]);
        float v0 = __ldg(&g_cval[i]),     v1 = __ldg(&g_cval[i + 1]);
        float v2 = __ldg(&g_cval[i + 2]), v3 = __ldg(&g_cval[i + 3]);
        float2 b0 = __ldg((const float2*)(w + (size_t)r0 * HIDD) + t);
        float2 b1 = __ldg((const float2*)(w + (size_t)r1 * HIDD) + t);
        float2 b2 = __ldg((const float2*)(w + (size_t)r2 * HIDD) + t);
        float2 b3 = __ldg((const float2*)(w + (size_t)r3 * HIDD) + t);
        ax = fmaf(v0, b0.x, ax); ay = fmaf(v0, b0.y, ay);
        ax = fmaf(v1, b1.x, ax); ay = fmaf(v1, b1.y, ay);
        ax = fmaf(v2, b2.x, ax); ay = fmaf(v2, b2.y, ay);
        ax = fmaf(v3, b3.x, ax); ay = fmaf(v3, b3.y, ay);
    }
    for (; i < i1; i++) {
        int r = __ldg(&g_cidx[i]);
        float v = __ldg(&g_cval[i]);
        float2 b = __ldg((const float2*)(w + (size_t)r * HIDD) + t);
        ax = fmaf(v, b.x, ax); ay = fmaf(v, b.y, ay);
    }
    atomicAdd(&g_hid[2 * t], ax);
    atomicAdd(&g_hid[2 * t + 1], ay);
}

// ---------------- fc2 + final relu (single block) ----------------
__global__ void k_fc2out(const float* __restrict__ b1v, const float* __restrict__ w2,
                         const float* __restrict__ b2v, float* __restrict__ out) {
    __shared__ float hs[HIDD];
    int t = threadIdx.x;
    for (int i = t; i < HIDD; i += 256) {
        float h = g_hid[i] + __ldg(&b1v[i]);
        hs[i] = h > 0.f ? h : 0.f;
    }
    __syncthreads();
    if (t < FINAL) {
        float a0 = 0.f, a1 = 0.f;
        // HIDD = 450 is even: the pair loop covers ALL rows; no odd tail.
#pragma unroll 5
        for (int h = 0; h < HIDD; h += 2) {
            a0 = fmaf(hs[h],     __ldg(&w2[h * FINAL + t]),       a0);
            a1 = fmaf(hs[h + 1], __ldg(&w2[(h + 1) * FINAL + t]), a1);
        }
        float v = a0 + a1 + __ldg(&b2v[t]);
        out[t] = v > 0.f ? v : 0.f;
    }
}

// ---------------- launcher ----------------
extern "C" void kernel_launch(void* const* d_in, const int* in_sizes, int n_in,
                              void* d_out, int out_size) {
    const float* x        = (const float*)d_in[0];
    const int*   ei       = (const int*)  d_in[1];
    const float* ea       = (const float*)d_in[2];
    const float* mlp_w1   = (const float*)d_in[3];
    const float* mlp_b1   = (const float*)d_in[4];
    const float* mlp_w2   = (const float*)d_in[5];
    const float* mlp_b2   = (const float*)d_in[6];
    const float* nn_root  = (const float*)d_in[7];
    const float* nn_bias  = (const float*)d_in[8];
    const float* gat_w    = (const float*)d_in[9];
    const float* att_src  = (const float*)d_in[10];
    const float* att_dst  = (const float*)d_in[11];
    const float* gat_bias = (const float*)d_in[12];
    const float* fc1_w    = (const float*)d_in[13];
    const float* fc1_b    = (const float*)d_in[14];
    const float* fc2_w    = (const float*)d_in[15];
    const float* fc2_b    = (const float*)d_in[16];
    float* out = (float*)d_out;

    k_init<<<(NN + 255) / 256, 256>>>();
    k_hist<<<(EE + 255) / 256, 256>>>(ei);
    k_scan<<<1, 256>>>();
    k_scatter<<<(EE + 255) / 256, 256>>>(ei, x, ea);
    k_S<<<NN / 8, 256>>>(mlp_w1, mlp_b1);
    k_x1xl<<<NN / 16, 256>>>(x, mlp_w2, mlp_b2, nn_root, nn_bias,
                             gat_w, att_src, att_dst);
    k_gat<<<NN / 8, 256>>>(gat_bias);
    k_fc1<<<1024, 256>>>(fc1_w);
    k_fc2out<<<1, 256>>>(fc1_b, fc2_w, fc2_b, out);
}